// round 16
// baseline (speedup 1.0000x reference)
#include <cuda_runtime.h>
#include <cuda_fp16.h>
#include <cstdint>

// ---------------------------------------------------------------------------
// InfoNCE supervised-contrastive loss — SYMMETRIC strip-pair fp16 HMMA,
// persistent CTAs with a cross-job chunk stream + fused finalize.
//   k1: label width detect (i64/i32) -> i32; zero accumulators; reset g_done
//   k2: normalize rows (warp/row, vectorized), fp16 K-chunk-major PRE-SWIZZLED
//   k3: 296 persistent CTAs (2/SM); jobs = 2080 strip pairs (p<=q); 3-slot
//       A/B ring streams chunks across job boundaries (epilogue of job i
//       overlaps DMA of job i+1); mma.sync.m16n8k16.f16; fused ex2 epilogue
//       -> row sums (p) + shfl-reduced column sums (q); LAST CTA reduces
//       all 8192 rows and writes the scalar.
// ---------------------------------------------------------------------------

#define NB      8192
#define ND      256
#define SROWS   128
#define NSTRIP  64
#define NJOBS   (NSTRIP * (NSTRIP + 1) / 2)   // 2080
#define KC      64
#define NTHR    256
#define NCTA    296
#define CHUNK_ELEMS (NB * KC)

__device__ __align__(1024) __half g_e[NB * ND];   // [4][8192][64] swizzled fp16
__device__ int   g_lab[NB];
__device__ float g_sall[NB];
__device__ float g_spos[NB];
__device__ unsigned int g_done;

// ---- smem layout (bytes) ----------------------------------------------------
#define A_OFF      0           // 3 slots x [128][64] fp16 swizzled = 48 KB
#define B_OFF      49152       // 3 slots = 48 KB
#define RSALL_OFF  98304       // 128 floats
#define RSPOS_OFF  98816
#define CSALL_OFF  99328
#define CSPOS_OFF  99840
#define CTRL_OFF   100352      // 3 mbarriers
#define SMEM_TOTAL 100384

// ---- PTX helpers ------------------------------------------------------------
__device__ __forceinline__ uint32_t smem_u32(const void* p) {
    uint32_t a;
    asm("{ .reg .u64 t; cvta.to.shared.u64 t, %1; cvt.u32.u64 %0, t; }" : "=r"(a) : "l"(p));
    return a;
}
__device__ __forceinline__ uint32_t sw128(uint32_t off) {
    return off ^ ((off >> 3) & 0x70);
}
__device__ __forceinline__ float ex2(float x) {
    float y;
    asm("ex2.approx.ftz.f32 %0, %1;" : "=f"(y) : "f"(x));
    return y;
}
#define MBAR_INIT(addr, cnt) \
    asm volatile("mbarrier.init.shared.b64 [%0], %1;" :: "r"(addr), "r"((uint32_t)(cnt)) : "memory")
#define MBAR_EXPECT_TX(addr, bytes) \
    asm volatile("mbarrier.arrive.expect_tx.shared.b64 _, [%0], %1;" :: "r"(addr), "r"((uint32_t)(bytes)) : "memory")
#define MBAR_WAIT(addr, parity) do {                                                   \
    asm volatile("{\n\t.reg .pred P1;\n\t"                                             \
        "WAIT_LP_%=:\n\t"                                                              \
        "mbarrier.try_wait.parity.acquire.cta.shared::cta.b64 P1, [%0], %1, 0x989680;\n\t" \
        "@P1 bra.uni WAIT_DN_%=;\n\t"                                                  \
        "bra.uni WAIT_LP_%=;\n\t"                                                      \
        "WAIT_DN_%=:\n\t}"                                                             \
        :: "r"(addr), "r"((uint32_t)(parity)) : "memory");                             \
} while (0)
__device__ __forceinline__ void bulk_ld(uint32_t dst, const void* src,
                                        uint32_t bytes, uint32_t mbar) {
    asm volatile(
        "cp.async.bulk.shared::cta.global.mbarrier::complete_tx::bytes [%0], [%1], %2, [%3];"
        :: "r"(dst), "l"(src), "r"(bytes), "r"(mbar) : "memory");
}
__device__ __forceinline__ void ldsm4(uint32_t* r, uint32_t addr) {
    asm volatile("ldmatrix.sync.aligned.m8n8.x4.shared.b16 {%0,%1,%2,%3}, [%4];"
        : "=r"(r[0]), "=r"(r[1]), "=r"(r[2]), "=r"(r[3]) : "r"(addr));
}
__device__ __forceinline__ void mma_f16(float* d, const uint32_t* a, const uint32_t* b) {
    asm volatile(
        "mma.sync.aligned.m16n8k16.row.col.f32.f16.f16.f32 "
        "{%0,%1,%2,%3},{%4,%5,%6,%7},{%8,%9},{%0,%1,%2,%3};"
        : "+f"(d[0]), "+f"(d[1]), "+f"(d[2]), "+f"(d[3])
        : "r"(a[0]), "r"(a[1]), "r"(a[2]), "r"(a[3]), "r"(b[0]), "r"(b[1]));
}

// job j (0..2079) -> strip pair (p <= q)
__device__ __forceinline__ void decode_job(int j, int& p, int& q) {
    int pp = (int)((129.0f - sqrtf(16641.0f - 8.0f * (float)j)) * 0.5f);
    while (pp > 0 && pp * (129 - pp) / 2 > j) --pp;
    while ((pp + 1) * (129 - (pp + 1)) / 2 <= j) ++pp;
    p = pp;
    q = pp + (j - pp * (129 - pp) / 2);
}

// issue DMA for flat chunk index ci (job = bid + (ci>>2)*NCTA, kc = ci&3)
__device__ __forceinline__ void issue_chunk(uint32_t sb, int ci, int bid) {
    const int jg = bid + (ci >> 2) * NCTA;
    int p, q;
    decode_job(jg, p, q);
    const int kc = ci & 3, slot = ci % 3;
    const uint32_t mb = sb + CTRL_OFF + 8 * slot;
    MBAR_EXPECT_TX(mb, 32768);
    bulk_ld(sb + A_OFF + slot * 16384,
            g_e + (size_t)kc * CHUNK_ELEMS + (size_t)(p * SROWS) * KC, 16384, mb);
    bulk_ld(sb + B_OFF + slot * 16384,
            g_e + (size_t)kc * CHUNK_ELEMS + (size_t)(q * SROWS) * KC, 16384, mb);
}

// ---------------------------------------------------------------------------
__global__ void convert_labels_kernel(const int* __restrict__ raw) {
    __shared__ int nz;
    if (threadIdx.x == 0) { nz = 0; g_done = 0u; }
    __syncthreads();
    int local = 0;
    for (int i = threadIdx.x; i < NB / 2; i += blockDim.x)
        local |= (raw[2 * i + 1] != 0);
    if (local) atomicOr(&nz, 1);
    __syncthreads();
    const bool is64 = (nz == 0);
    for (int i = threadIdx.x; i < NB; i += blockDim.x) {
        g_lab[i]  = is64 ? raw[2 * i] : raw[i];
        g_sall[i] = 0.f;
        g_spos[i] = 0.f;
    }
}

// ---------------------------------------------------------------------------
__global__ void normalize_kernel(const float* __restrict__ emb) {
    const int w = threadIdx.x >> 5, lane = threadIdx.x & 31;
    const int r = blockIdx.x * 8 + w;
    const float4 x0 = *(const float4*)(emb + r * ND + lane * 8);
    const float4 x1 = *(const float4*)(emb + r * ND + lane * 8 + 4);
    float ss = x0.x * x0.x + x0.y * x0.y + x0.z * x0.z + x0.w * x0.w
             + x1.x * x1.x + x1.y * x1.y + x1.z * x1.z + x1.w * x1.w;
    #pragma unroll
    for (int off = 16; off > 0; off >>= 1)
        ss += __shfl_xor_sync(0xffffffffu, ss, off);
    const float rn = 1.0f / fmaxf(sqrtf(ss), 1e-12f);

    union { uint4 u; __half h[8]; } pk;
    pk.h[0] = __float2half(x0.x * rn); pk.h[1] = __float2half(x0.y * rn);
    pk.h[2] = __float2half(x0.z * rn); pk.h[3] = __float2half(x0.w * rn);
    pk.h[4] = __float2half(x1.x * rn); pk.h[5] = __float2half(x1.y * rn);
    pk.h[6] = __float2half(x1.z * rn); pk.h[7] = __float2half(x1.w * rn);

    const int kc = lane >> 3, k16 = lane & 7;
    __half* dst = g_e + (uint32_t)kc * CHUNK_ELEMS
                + (sw128((uint32_t)r * 128 + (uint32_t)k16 * 16) >> 1);
    *(uint4*)dst = pk.u;
}

// ---------------------------------------------------------------------------
__global__ void __launch_bounds__(NTHR, 2) gemm_lse_kernel(float* __restrict__ out) {
    extern __shared__ char smem[];
    const uint32_t sb = smem_u32(smem);
    float* rsall = (float*)(smem + RSALL_OFF);
    float* rspos = (float*)(smem + RSPOS_OFF);
    float* csall = (float*)(smem + CSALL_OFF);
    float* cspos = (float*)(smem + CSPOS_OFF);

    const int tid = threadIdx.x, wid = tid >> 5, lane = tid & 31;
    const int wm = wid >> 1;             // 0..3 (32 rows each)
    const int wn = wid & 1;              // 0..1 (64 cols each)
    const int bid = (int)blockIdx.x;

    const int njobs_local = (bid < NJOBS) ? ((NJOBS - 1 - bid) / NCTA + 1) : 0;
    const int total_chunks = njobs_local * 4;

    // prologue: zero accumulators + barriers + first 3 chunks in flight
    if (tid < 128) { rsall[tid] = 0.f; rspos[tid] = 0.f; }
    else { csall[tid - 128] = 0.f; cspos[tid - 128] = 0.f; }
    if (tid == 0) {
        #pragma unroll
        for (int s = 0; s < 3; ++s) MBAR_INIT(sb + CTRL_OFF + 8 * s, 1);
    }
    __syncthreads();
    if (tid == 0) {
        for (int ci = 0; ci < 3 && ci < total_chunks; ++ci)
            issue_chunk(sb, ci, bid);
    }

    // ldmatrix lane addressing constants
    const uint32_t a_row = ((lane >> 3) & 1) * 8 + (lane & 7);
    const uint32_t a_kb  = ((lane >> 4) & 1) * 16;
    const uint32_t b_row = ((lane >> 4) & 1) * 8 + (lane & 7);
    const uint32_t b_kb  = ((lane >> 3) & 1) * 16;
    const uint32_t xm    = (uint32_t)(lane & 7) << 4;
    const uint32_t arow_off = (wm * 32 + a_row) * 128;
    const uint32_t brow_off = (wn * 64 + b_row) * 128;
    const float C2 = 20.609929230246954f;   // log2(e)/T
    const int rlb = wm * 32 + (lane >> 2);

    for (int jiter = 0; jiter < njobs_local; ++jiter) {
        int p, q;
        decode_job(bid + jiter * NCTA, p, q);
        const bool isdiag = (p == q);
        const int prow = p * SROWS, qrow = q * SROWS;

        float acc[2][8][4];
        #pragma unroll
        for (int mt = 0; mt < 2; ++mt)
            #pragma unroll
            for (int nt = 0; nt < 8; ++nt)
                #pragma unroll
                for (int e = 0; e < 4; ++e) acc[mt][nt][e] = 0.f;

        #pragma unroll
        for (int kc = 0; kc < 4; ++kc) {
            const int ci = jiter * 4 + kc;
            const int slot = ci % 3;
            MBAR_WAIT(sb + CTRL_OFF + 8 * slot, (ci / 3) & 1);
            const uint32_t sa   = sb + A_OFF + slot * 16384;
            const uint32_t sbuf = sb + B_OFF + slot * 16384;
            #pragma unroll
            for (int k16 = 0; k16 < 4; ++k16) {
                const uint32_t akx = ((uint32_t)(k16 * 32) + a_kb) ^ xm;
                const uint32_t bkx = ((uint32_t)(k16 * 32) + b_kb) ^ xm;
                uint32_t ah[2][4], bh[4][4];
                #pragma unroll
                for (int mt = 0; mt < 2; ++mt)
                    ldsm4(ah[mt], sa + arow_off + mt * 2048 + akx);
                #pragma unroll
                for (int pp = 0; pp < 4; ++pp)
                    ldsm4(bh[pp], sbuf + brow_off + pp * 2048 + bkx);
                #pragma unroll
                for (int mt = 0; mt < 2; ++mt)
                    #pragma unroll
                    for (int nt = 0; nt < 8; ++nt)
                        mma_f16(acc[mt][nt], ah[mt], &bh[nt >> 1][(nt & 1) * 2]);
            }
            __syncthreads();                 // slot drained by all warps
            if (tid == 0 && ci + 3 < total_chunks)
                issue_chunk(sb, ci + 3, bid);   // may belong to the NEXT job
        }

        // ---- epilogue: rows (p) AND columns (q); labels straight from L1 ----
        int rlab[4];
        rlab[0] = g_lab[prow + rlb];      rlab[1] = g_lab[prow + rlb + 8];
        rlab[2] = g_lab[prow + rlb + 16]; rlab[3] = g_lab[prow + rlb + 24];

        float psall[4] = {0.f, 0.f, 0.f, 0.f};
        float pspos[4] = {0.f, 0.f, 0.f, 0.f};
        float colall[16], colpos[16];

        #pragma unroll
        for (int nt = 0; nt < 8; ++nt) {
            const int cl0 = wn * 64 + nt * 8 + 2 * (lane & 3);
            const int cl1 = cl0 + 1;
            const int lc0 = g_lab[qrow + cl0], lc1 = g_lab[qrow + cl1];
            float ca0 = 0.f, ca1 = 0.f, cp0 = 0.f, cp1 = 0.f;
            #pragma unroll
            for (int mt = 0; mt < 2; ++mt) {
                const int rl0 = rlb + mt * 16;
                const int rl1 = rl0 + 8;
                const float* a4 = acc[mt][nt];
                float v0 = ex2(fmaf(a4[0], C2, -C2));
                float v1 = ex2(fmaf(a4[1], C2, -C2));
                float v2 = ex2(fmaf(a4[2], C2, -C2));
                float v3 = ex2(fmaf(a4[3], C2, -C2));
                if (isdiag) {
                    if (rl0 == cl0) v0 = 0.f;
                    if (rl0 == cl1) v1 = 0.f;
                    if (rl1 == cl0) v2 = 0.f;
                    if (rl1 == cl1) v3 = 0.f;
                }
                psall[2 * mt]     += v0 + v1;
                psall[2 * mt + 1] += v2 + v3;
                ca0 += v0 + v2;
                ca1 += v1 + v3;
                if (lc0 == rlab[2 * mt])     { pspos[2 * mt]     += v0; cp0 += v0; }
                if (lc1 == rlab[2 * mt])     { pspos[2 * mt]     += v1; cp1 += v1; }
                if (lc0 == rlab[2 * mt + 1]) { pspos[2 * mt + 1] += v2; cp0 += v2; }
                if (lc1 == rlab[2 * mt + 1]) { pspos[2 * mt + 1] += v3; cp1 += v3; }
            }
            colall[2 * nt] = ca0; colall[2 * nt + 1] = ca1;
            colpos[2 * nt] = cp0; colpos[2 * nt + 1] = cp1;
        }

        atomicAdd(&rsall[rlb],      psall[0]);
        atomicAdd(&rsall[rlb + 8],  psall[1]);
        atomicAdd(&rsall[rlb + 16], psall[2]);
        atomicAdd(&rsall[rlb + 24], psall[3]);
        atomicAdd(&rspos[rlb],      pspos[0]);
        atomicAdd(&rspos[rlb + 8],  pspos[1]);
        atomicAdd(&rspos[rlb + 16], pspos[2]);
        atomicAdd(&rspos[rlb + 24], pspos[3]);

        if (!isdiag) {
            #pragma unroll
            for (int i = 0; i < 16; ++i) {
                #pragma unroll
                for (int off = 4; off <= 16; off <<= 1) {
                    colall[i] += __shfl_xor_sync(0xffffffffu, colall[i], off);
                    colpos[i] += __shfl_xor_sync(0xffffffffu, colpos[i], off);
                }
            }
            if (lane < 4) {
                #pragma unroll
                for (int nt = 0; nt < 8; ++nt) {
                    const int c0 = wn * 64 + nt * 8 + 2 * lane;
                    atomicAdd(&csall[c0],     colall[2 * nt]);
                    atomicAdd(&csall[c0 + 1], colall[2 * nt + 1]);
                    atomicAdd(&cspos[c0],     colpos[2 * nt]);
                    atomicAdd(&cspos[c0 + 1], colpos[2 * nt + 1]);
                }
            }
        }
        __syncthreads();

        // flush to global, then re-zero for the next job (thread-local order
        // guarantees read-before-clear; chunk syncs order clear vs next atomics)
        if (tid < 128) {
            atomicAdd(&g_sall[prow + tid], rsall[tid]);
            atomicAdd(&g_spos[prow + tid], rspos[tid]);
            rsall[tid] = 0.f; rspos[tid] = 0.f;
        } else {
            const int t = tid - 128;
            if (!isdiag) {
                atomicAdd(&g_sall[qrow + t], csall[t]);
                atomicAdd(&g_spos[qrow + t], cspos[t]);
            }
            csall[t] = 0.f; cspos[t] = 0.f;
        }
    }

    // ================= fused finalize: last CTA reduces everything ==========
    __shared__ int is_last;
    __shared__ float fsum[8];
    __shared__ int   fcnt[8];
    __threadfence();
    __syncthreads();
    if (tid == 0) {
        unsigned int d = atomicAdd(&g_done, 1u);
        is_last = (d == NCTA - 1u);
    }
    __syncthreads();
    if (!is_last) return;

    float ls = 0.f; int lc = 0;
    #pragma unroll
    for (int i = 0; i < 32; ++i) {
        const int r = tid + NTHR * i;
        const float sp = __ldcg(&g_spos[r]);
        if (sp > 0.f) { ls += __logf(__ldcg(&g_sall[r]) / sp); lc++; }
    }
    #pragma unroll
    for (int off = 16; off > 0; off >>= 1) {
        ls += __shfl_xor_sync(0xffffffffu, ls, off);
        lc += __shfl_xor_sync(0xffffffffu, lc, off);
    }
    if (lane == 0) { fsum[wid] = ls; fcnt[wid] = lc; }
    __syncthreads();
    if (wid == 0 && lane < 8) {
        ls = fsum[lane]; lc = fcnt[lane];
        #pragma unroll
        for (int off = 4; off > 0; off >>= 1) {
            ls += __shfl_xor_sync(0x000000ffu, ls, off);
            lc += __shfl_xor_sync(0x000000ffu, lc, off);
        }
        if (lane == 0) out[0] = (lc > 0) ? (ls / (float)lc) : 0.0f;
    }
}

// ---------------------------------------------------------------------------
extern "C" void kernel_launch(void* const* d_in, const int* in_sizes, int n_in,
                              void* d_out, int out_size) {
    const float* emb = (const float*)d_in[0];
    const int*   lab = (const int*)d_in[1];
    float*       out = (float*)d_out;

    cudaFuncSetAttribute(gemm_lse_kernel,
                         cudaFuncAttributeMaxDynamicSharedMemorySize, SMEM_TOTAL);

    convert_labels_kernel<<<1, 1024>>>(lab);
    normalize_kernel<<<NB / 8, 256>>>(emb);
    gemm_lse_kernel<<<NCTA, NTHR, SMEM_TOTAL>>>(out);
}